// round 12
// baseline (speedup 1.0000x reference)
#include <cuda_runtime.h>

// Permutation: x[B=16, C=64, H=256, W=256] fp32
//   out[b][i][j][k][cc][hh][ww] = x[b][i*32+cc][j*16+hh][k*16+ww]
//
// FINAL (R8): smem-tiled block transpose at the HBM mixed-stream wall
// (~7.15 TB/s effective, 89% of spec; DRAM cycles-active ~81%).
//   - CTA = (b,i,cc,j): reads ONE contiguous 16 KB input run (coalesced
//     128B warp loads, front-batched MLP=4, streaming .cs)
//   - stages through 17 KB smem, rows padded 64->68 f4 -> conflict-free
//     128-bit STS (input order) and LDS (output order)
//   - writes 16 chunks of 1 KB contiguous (coalesced, streaming .cs)
//   - hybrid grid order: low 2 bits cc (co-scheduled CTAs chain 4 KB write
//     runs), next 4 bits j (adjacent 16 KB read tiles)
//   - 32 regs, occ ~95%, single __syncthreads per 16 KB
// Measured equivalent within noise across MLP depth, occupancy, cohort
// ordering, and async-bulk write path: memory-system bound, not kernel bound.

static constexpr unsigned NBLOCKS = 16u * 2u * 32u * 16u;  // 16384

__global__ __launch_bounds__(256)
void reshape_78271484002964_kernel(const float4* __restrict__ in,
                                   float4* __restrict__ out) {
    __shared__ float4 sm[16 * 68];  // [hh][k*4+ww4 padded to 68] = 17408 B

    unsigned bid  = blockIdx.x;
    unsigned c_lo = bid & 3u;            // write adjacency (out bits 6..7)
    unsigned j    = (bid >> 2) & 15u;    // read adjacency (adjacent 16KB tiles)
    unsigned c_hi = (bid >> 6) & 7u;
    unsigned i    = (bid >> 9) & 1u;
    unsigned b    = bid >> 10;
    unsigned cc   = (c_hi << 2) | c_lo;

    unsigned channel = (b << 6) + (i << 5) + cc;
    const float4* src = in + (channel << 14) + (j << 10);

    unsigned t = threadIdx.x;

    // ---- Phase 1: stream 16 KB contiguous input (front-batched) ----
    float4 v0 = __ldcs(src + t);
    float4 v1 = __ldcs(src + t + 256u);
    float4 v2 = __ldcs(src + t + 512u);
    float4 v3 = __ldcs(src + t + 768u);

    // input-linear offset o: hh = o>>6, kw = o&63 ; smem addr = hh*68 + kw
    sm[((t        ) >> 6) * 68u + ((t        ) & 63u)] = v0;
    sm[((t + 256u ) >> 6) * 68u + ((t + 256u ) & 63u)] = v1;
    sm[((t + 512u ) >> 6) * 68u + ((t + 512u ) & 63u)] = v2;
    sm[((t + 768u ) >> 6) * 68u + ((t + 768u ) & 63u)] = v3;

    __syncthreads();

    // ---- Phase 2: emit in output order ----
    // out f4 idx = ww4 | hh<<2 | cc<<6 | k<<11 | j<<15 | i<<19 | b<<20
    unsigned out_base = (cc << 6) + (j << 15) + (i << 19) + (b << 20);

#pragma unroll
    for (unsigned it = 0; it < 4u; ++it) {
        unsigned p   = t + it * 256u;        // output-linear offset in tile
        unsigned ww4 = p & 3u;
        unsigned hh  = (p >> 2) & 15u;
        unsigned k   = p >> 6;
        float4 v = sm[hh * 68u + (k << 2) + ww4];
        __stcs(&out[out_base + (k << 11) + (p & 63u)], v);
    }
}

extern "C" void kernel_launch(void* const* d_in, const int* in_sizes, int n_in,
                              void* d_out, int out_size) {
    const float4* in  = (const float4*)d_in[0];
    float4*       out = (float4*)d_out;

    reshape_78271484002964_kernel<<<NBLOCKS, 256>>>(in, out);
}

// round 13
// speedup vs baseline: 1.0039x; 1.0039x over previous
#include <cuda_runtime.h>

// Permutation: x[B=16, C=64, H=256, W=256] fp32
//   out[b][i][j][k][cc][hh][ww] = x[b][i*32+cc][j*16+hh][k*16+ww]
//
// FINAL (R8): smem-tiled block transpose at the HBM mixed-stream wall
// (~7.15 TB/s effective, ~89% of spec; DRAM cycles-active ~81%).
//   - CTA = (b,i,cc,j): reads ONE contiguous 16 KB input run (coalesced
//     128B warp loads, front-batched MLP=4, streaming .cs)
//   - stages through 17 KB smem, rows padded 64->68 f4 -> conflict-free
//     128-bit STS (input order) and LDS (output order)
//   - writes 16 chunks of 1 KB contiguous (coalesced, streaming .cs)
//   - hybrid grid order: low 2 bits cc (co-scheduled CTAs chain 4 KB write
//     runs), next 4 bits j (adjacent 16 KB read tiles)
//   - 32 regs, occ ~92-95%, single __syncthreads per 16 KB
// Convergence evidence: nine designs (MLP 1/4/8 direct copies, four smem
// cohort orderings, double-buffered + overlapped pipelines, async-bulk
// writes) all plateau at DRAM 79-81% / kernel 75-77us. Memory-system bound.

static constexpr unsigned NBLOCKS = 16u * 2u * 32u * 16u;  // 16384

__global__ __launch_bounds__(256)
void reshape_78271484002964_kernel(const float4* __restrict__ in,
                                   float4* __restrict__ out) {
    __shared__ float4 sm[16 * 68];  // [hh][k*4+ww4 padded to 68] = 17408 B

    unsigned bid  = blockIdx.x;
    unsigned c_lo = bid & 3u;            // write adjacency (out bits 6..7)
    unsigned j    = (bid >> 2) & 15u;    // read adjacency (adjacent 16KB tiles)
    unsigned c_hi = (bid >> 6) & 7u;
    unsigned i    = (bid >> 9) & 1u;
    unsigned b    = bid >> 10;
    unsigned cc   = (c_hi << 2) | c_lo;

    unsigned channel = (b << 6) + (i << 5) + cc;
    const float4* src = in + (channel << 14) + (j << 10);

    unsigned t = threadIdx.x;

    // ---- Phase 1: stream 16 KB contiguous input (front-batched) ----
    float4 v0 = __ldcs(src + t);
    float4 v1 = __ldcs(src + t + 256u);
    float4 v2 = __ldcs(src + t + 512u);
    float4 v3 = __ldcs(src + t + 768u);

    // input-linear offset o: hh = o>>6, kw = o&63 ; smem addr = hh*68 + kw
    sm[((t        ) >> 6) * 68u + ((t        ) & 63u)] = v0;
    sm[((t + 256u ) >> 6) * 68u + ((t + 256u ) & 63u)] = v1;
    sm[((t + 512u ) >> 6) * 68u + ((t + 512u ) & 63u)] = v2;
    sm[((t + 768u ) >> 6) * 68u + ((t + 768u ) & 63u)] = v3;

    __syncthreads();

    // ---- Phase 2: emit in output order ----
    // out f4 idx = ww4 | hh<<2 | cc<<6 | k<<11 | j<<15 | i<<19 | b<<20
    unsigned out_base = (cc << 6) + (j << 15) + (i << 19) + (b << 20);

#pragma unroll
    for (unsigned it = 0; it < 4u; ++it) {
        unsigned p   = t + it * 256u;        // output-linear offset in tile
        unsigned ww4 = p & 3u;
        unsigned hh  = (p >> 2) & 15u;
        unsigned k   = p >> 6;
        float4 v = sm[hh * 68u + (k << 2) + ww4];
        __stcs(&out[out_base + (k << 11) + (p & 63u)], v);
    }
}

extern "C" void kernel_launch(void* const* d_in, const int* in_sizes, int n_in,
                              void* d_out, int out_size) {
    const float4* in  = (const float4*)d_in[0];
    float4*       out = (float4*)d_out;

    reshape_78271484002964_kernel<<<NBLOCKS, 256>>>(in, out);
}